// round 4
// baseline (speedup 1.0000x reference)
#include <cuda_runtime.h>
#include <math.h>

#define N_NODES 50000
#define N_EDGES 1600000
#define HID 32
#define HOR 12
#define NBLK 196                 // ceil(50000/256)

// ---------------- scratch (static device allocation) ----------------
__device__ float g_deg[N_NODES];
__device__ float g_dinv[N_NODES];
__device__ int   g_cnt[N_NODES];          // in-degree by dst
__device__ int   g_off[N_NODES + 1];      // CSR offsets
__device__ int   g_cur[N_NODES];          // scatter cursors
__device__ int   g_bsum[NBLK];
__device__ int   g_boff[NBLK];
__device__ float4 g_Xs4[N_NODES * HID / 4];   // dinv[s]*x[s]
__device__ float4 g_h0s4[N_NODES * HID / 4];  // dinv[s]*h0[s]
__device__ unsigned long long g_epack[N_EDGES]; // (w<<32)|src binned by dst
__device__ float g_LX[N_NODES * HID];
__device__ float g_Lh[N_NODES * HID];
__device__ int   g_hflag;

// ---------------- init: zero counters, probe h0 ----------------
__global__ void k_init(const float4* __restrict__ h04) {
    int i = blockIdx.x * blockDim.x + threadIdx.x;
    if (i == 0) g_hflag = 0;
    if (i < N_NODES) { g_deg[i] = 0.f; g_cnt[i] = 0; }
    if (i < N_NODES * HID / 4) {
        float4 v = h04[i];
        if (v.x != 0.f || v.y != 0.f || v.z != 0.f || v.w != 0.f) g_hflag = 1;
    }
}

// ---------------- deg by src (weighted) + count by dst ----------------
__global__ void k_deg(const int* __restrict__ src,
                      const int* __restrict__ dst,
                      const float* __restrict__ w) {
    int e = blockIdx.x * blockDim.x + threadIdx.x;
    if (e < N_EDGES) {
        int s = src[e];
        int d = dst[e];
        if (s >= 0 && s < N_NODES) atomicAdd(&g_deg[s], w[e]);
        if (d >= 0 && d < N_NODES) atomicAdd(&g_cnt[d], 1);
    }
}

// ---------------- per-block sums of cnt + dinv ----------------
__global__ void k_scan1() {
    __shared__ int ws[8];
    int t = threadIdx.x;
    int i = blockIdx.x * 256 + t;
    int v = (i < N_NODES) ? g_cnt[i] : 0;
    if (i < N_NODES) {
        float d = g_deg[i];
        g_dinv[i] = d > 0.f ? rsqrtf(d) : 0.f;
    }
    #pragma unroll
    for (int o = 16; o; o >>= 1) v += __shfl_down_sync(0xffffffffu, v, o);
    if ((t & 31) == 0) ws[t >> 5] = v;
    __syncthreads();
    if (t == 0) {
        int s = 0;
        #pragma unroll
        for (int k = 0; k < 8; k++) s += ws[k];
        g_bsum[blockIdx.x] = s;
    }
}

// ---------------- scan the 196 block sums (1 warp) ----------------
__global__ void k_bscan() {
    int lane = threadIdx.x;
    int run = 0;
    for (int base = 0; base < NBLK; base += 32) {
        int idx = base + lane;
        int orig = (idx < NBLK) ? g_bsum[idx] : 0;
        int incl = orig;
        #pragma unroll
        for (int o = 1; o < 32; o <<= 1) {
            int u = __shfl_up_sync(0xffffffffu, incl, o);
            if (lane >= o) incl += u;
        }
        if (idx < NBLK) g_boff[idx] = run + incl - orig;
        run += __shfl_sync(0xffffffffu, incl, 31);
    }
    if (lane == 0) g_off[N_NODES] = run;
}

// ---------------- block-local exclusive scan -> offsets + cursors ----------------
__global__ void k_offsets() {
    __shared__ int wsum[8];
    int t = threadIdx.x;
    int b = blockIdx.x;
    int i = b * 256 + t;
    int v = (i < N_NODES) ? g_cnt[i] : 0;
    int incl = v;
    #pragma unroll
    for (int o = 1; o < 32; o <<= 1) {
        int u = __shfl_up_sync(0xffffffffu, incl, o);
        if ((t & 31) >= o) incl += u;
    }
    if ((t & 31) == 31) wsum[t >> 5] = incl;
    __syncthreads();
    if (t < 8) {
        int ws = wsum[t];
        #pragma unroll
        for (int o = 1; o < 8; o <<= 1) {
            int u = __shfl_up_sync(0xffu, ws, o);
            if (t >= o) ws += u;
        }
        wsum[t] = ws;   // inclusive warp sums
    }
    __syncthreads();
    int woff = (t >= 32) ? wsum[(t >> 5) - 1] : 0;
    int excl = g_boff[b] + woff + incl - v;
    if (i < N_NODES) { g_off[i] = excl; g_cur[i] = excl; }
}

// ---------------- pre-scale: Xs = dinv[node]*x, h0s likewise ----------------
__global__ void k_xs(const float4* __restrict__ x4, const float4* __restrict__ h04) {
    int i = blockIdx.x * blockDim.x + threadIdx.x;
    if (i < N_NODES * HID / 4) {
        float di = g_dinv[i >> 3];   // 8 float4 per node
        float4 v = x4[i];
        v.x *= di; v.y *= di; v.z *= di; v.w *= di;
        g_Xs4[i] = v;
        if (g_hflag) {
            float4 h = h04[i];
            h.x *= di; h.y *= di; h.z *= di; h.w *= di;
            g_h0s4[i] = h;
        }
    }
}

// ---------------- scatter edges into dst-binned order ----------------
__global__ void k_scatter(const int* __restrict__ src,
                          const int* __restrict__ dst,
                          const float* __restrict__ w) {
    int e = blockIdx.x * blockDim.x + threadIdx.x;
    if (e < N_EDGES) {
        int d = dst[e];
        int s = src[e];
        if (s >= 0 && s < N_NODES && d >= 0 && d < N_NODES) {
            int pos = atomicAdd(&g_cur[d], 1);
            unsigned long long p =
                ((unsigned long long)__float_as_uint(w[e]) << 32) | (unsigned int)s;
            g_epack[pos] = p;
        }
    }
}

// ---------------- gather: one warp per dst node, no atomics ----------------
__global__ void __launch_bounds__(256) k_gather() {
    int wg = blockIdx.x * 8 + (threadIdx.x >> 5);
    if (wg >= N_NODES) return;
    int lane = threadIdx.x & 31;
    int beg = g_off[wg], end = g_off[wg + 1];
    const float* xs  = (const float*)g_Xs4;
    const float* h0s = (const float*)g_h0s4;
    int hf = g_hflag;

    float acc = 0.f, acch = 0.f;
    if (!hf) {
        for (int base = beg; base < end; base += 32) {
            unsigned long long p = 0;   // w=0 for inactive lanes -> contributes 0
            if (base + lane < end) p = g_epack[base + lane];
            #pragma unroll
            for (int j = 0; j < 32; j++) {
                unsigned long long pj = __shfl_sync(0xffffffffu, p, j);
                int   s  = (int)(pj & 0xffffffffu);
                float wv = __uint_as_float((unsigned int)(pj >> 32));
                acc += wv * __ldg(&xs[(size_t)s * HID + lane]);
            }
        }
    } else {
        for (int base = beg; base < end; base += 32) {
            unsigned long long p = 0;
            if (base + lane < end) p = g_epack[base + lane];
            #pragma unroll
            for (int j = 0; j < 32; j++) {
                unsigned long long pj = __shfl_sync(0xffffffffu, p, j);
                int   s  = (int)(pj & 0xffffffffu);
                float wv = __uint_as_float((unsigned int)(pj >> 32));
                acc  += wv * __ldg(&xs[(size_t)s * HID + lane]);
                acch += wv * __ldg(&h0s[(size_t)s * HID + lane]);
            }
        }
    }
    float di = -g_dinv[wg];
    g_LX[wg * HID + lane] = di * acc;
    if (hf) g_Lh[wg * HID + lane] = di * acch;
}

// ---------------- gates + LSTM cell + linear head, fused ----------------
__global__ void __launch_bounds__(128) k_gates(
        const float* __restrict__ x,
        const float* __restrict__ h0,
        const float* __restrict__ c0,
        const float* __restrict__ Wx,   // [4][2][32][32]
        const float* __restrict__ bx,
        const float* __restrict__ Wh,
        const float* __restrict__ bh,
        const float* __restrict__ wc,
        const float* __restrict__ b,
        const float* __restrict__ Wl,   // [32][12]
        const float* __restrict__ bl,
        float* __restrict__ out) {
    __shared__ float sWx[4 * 2 * 32 * 32];
    __shared__ float sU[16 * 4 * 32];
    __shared__ float sWl[HID * HOR];
    __shared__ float sbsum[4 * HID];
    __shared__ float swc[3 * HID];
    __shared__ float sbl[HOR];

    int tid = threadIdx.x;
    int nodeBase = blockIdx.x * 16;
    int hf = g_hflag;

    for (int i = tid; i < 8192; i += 128) sWx[i] = Wx[i];
    for (int i = tid; i < HID * HOR; i += 128) sWl[i] = Wl[i];
    if (tid < 4 * HID) sbsum[tid] = bx[tid] + bh[tid] + b[tid];
    if (tid < 3 * HID) swc[tid] = wc[tid];
    if (tid < HOR)     sbl[tid] = bl[tid];

    for (int i = tid; i < 16 * 2 * 32; i += 128) {
        int n = i >> 6, m = (i >> 5) & 1, k = i & 31;
        int node = nodeBase + n;
        float v = 0.f;
        if (node < N_NODES) v = m ? g_LX[node * HID + k] : x[node * HID + k];
        sU[(n * 4 + m) * 32 + k] = v;
    }
    if (hf) {
        for (int i = tid; i < 16 * 2 * 32; i += 128) {
            int n = i >> 6, m = (i >> 5) & 1, k = i & 31;
            int node = nodeBase + n;
            float v = 0.f;
            if (node < N_NODES) v = m ? g_Lh[node * HID + k] : h0[node * HID + k];
            sU[(n * 4 + 2 + m) * 32 + k] = v;
        }
    }
    __syncthreads();

    int warp = tid >> 5;
    int j = tid & 31;
    int nb = warp * 4;

    float acc[4][4];
    #pragma unroll
    for (int n = 0; n < 4; n++)
        #pragma unroll
        for (int g = 0; g < 4; g++) acc[n][g] = 0.f;

    if (!hf) {
        #pragma unroll
        for (int k = 0; k < 32; k++) {
            float wa[4], wb[4];
            #pragma unroll
            for (int g = 0; g < 4; g++) {
                wa[g] = sWx[g * 2048 +        k * 32 + j];
                wb[g] = sWx[g * 2048 + 1024 + k * 32 + j];
            }
            #pragma unroll
            for (int n = 0; n < 4; n++) {
                float xv  = sU[((nb + n) * 4 + 0) * 32 + k];
                float lxv = sU[((nb + n) * 4 + 1) * 32 + k];
                #pragma unroll
                for (int g = 0; g < 4; g++)
                    acc[n][g] += xv * wa[g] + lxv * wb[g];
            }
        }
    } else {
        #pragma unroll
        for (int k = 0; k < 32; k++) {
            float wa[4], wb[4], wha[4], whb[4];
            #pragma unroll
            for (int g = 0; g < 4; g++) {
                wa[g]  = sWx[g * 2048 +        k * 32 + j];
                wb[g]  = sWx[g * 2048 + 1024 + k * 32 + j];
                wha[g] = __ldg(&Wh[g * 2048 +        k * 32 + j]);
                whb[g] = __ldg(&Wh[g * 2048 + 1024 + k * 32 + j]);
            }
            #pragma unroll
            for (int n = 0; n < 4; n++) {
                float xv  = sU[((nb + n) * 4 + 0) * 32 + k];
                float lxv = sU[((nb + n) * 4 + 1) * 32 + k];
                float hv  = sU[((nb + n) * 4 + 2) * 32 + k];
                float lhv = sU[((nb + n) * 4 + 3) * 32 + k];
                #pragma unroll
                for (int g = 0; g < 4; g++)
                    acc[n][g] += xv * wa[g] + lxv * wb[g] + hv * wha[g] + lhv * whb[g];
            }
        }
    }

    float* oh = out;
    float* oH = out + (size_t)N_NODES * HOR;
    float* oC = oH + (size_t)N_NODES * HID;

    #pragma unroll
    for (int n = 0; n < 4; n++) {
        int node = nodeBase + nb + n;
        if (node < N_NODES) {
            float c0v = c0[node * HID + j];
            float preI = acc[n][0] + sbsum[0 * 32 + j] + swc[0 * 32 + j] * c0v;
            float preF = acc[n][1] + sbsum[1 * 32 + j] + swc[1 * 32 + j] * c0v;
            float preT = acc[n][2] + sbsum[2 * 32 + j];
            float I  = 1.f / (1.f + __expf(-preI));
            float Fg = 1.f / (1.f + __expf(-preF));
            float T  = tanhf(preT);
            float C  = Fg * c0v + I * T;
            float preO = acc[n][3] + sbsum[3 * 32 + j] + swc[2 * 32 + j] * C;
            float O  = 1.f / (1.f + __expf(-preO));
            float H  = O * tanhf(C);

            oH[node * HID + j] = H;
            oC[node * HID + j] = C;

            float rH = fmaxf(H, 0.f);
            float keep = 0.f;
            #pragma unroll
            for (int t = 0; t < HOR; t++) {
                float s = rH * sWl[j * HOR + t];
                s += __shfl_xor_sync(0xffffffffu, s, 16);
                s += __shfl_xor_sync(0xffffffffu, s, 8);
                s += __shfl_xor_sync(0xffffffffu, s, 4);
                s += __shfl_xor_sync(0xffffffffu, s, 2);
                s += __shfl_xor_sync(0xffffffffu, s, 1);
                if (j == t) keep = s + sbl[t];
            }
            if (j < HOR) oh[node * HOR + j] = keep;
        }
    }
}

// ---------------- launch ----------------
extern "C" void kernel_launch(void* const* d_in, const int* in_sizes, int n_in,
                              void* d_out, int out_size) {
    int iX, iEI, iEW, iWx, iBx, iWh, iBh, iWc, iB, iWl, iBl, iH0, iC0;
    if (n_in > 8 && in_sizes[8] == 2 * N_EDGES) {
        iWl = 0; iWh = 1; iWx = 2; iB = 3; iBl = 4; iBh = 5; iBx = 6;
        iC0 = 7; iEI = 8; iEW = 9; iH0 = 10; iWc = 11; iX = 12;
    } else {
        iX = 0; iEI = 1; iEW = 2; iWx = 3; iBx = 4; iWh = 5; iBh = 6;
        iWc = 7; iB = 8; iWl = 9; iBl = 10; iH0 = 11; iC0 = 12;
    }

    const float* x    = (const float*)d_in[iX];
    const int*   ei   = (const int*)d_in[iEI];     // int32 (JAX x64 off)
    const float* ew   = (const float*)d_in[iEW];
    const float* Wx   = (const float*)d_in[iWx];
    const float* bx   = (const float*)d_in[iBx];
    const float* Wh   = (const float*)d_in[iWh];
    const float* bh   = (const float*)d_in[iBh];
    const float* wc   = (const float*)d_in[iWc];
    const float* b    = (const float*)d_in[iB];
    const float* Wl   = (const float*)d_in[iWl];
    const float* bl   = (const float*)d_in[iBl];
    const float* h0   = (const float*)d_in[iH0];
    const float* c0   = (const float*)d_in[iC0];
    float*       out  = (float*)d_out;

    const int* src = ei;
    const int* dst = ei + N_EDGES;

    k_init<<<(N_NODES * HID / 4 + 255) / 256, 256>>>((const float4*)h0);
    k_deg<<<(N_EDGES + 255) / 256, 256>>>(src, dst, ew);
    k_scan1<<<NBLK, 256>>>();
    k_bscan<<<1, 32>>>();
    k_offsets<<<NBLK, 256>>>();
    k_xs<<<(N_NODES * HID / 4 + 255) / 256, 256>>>((const float4*)x, (const float4*)h0);
    k_scatter<<<(N_EDGES + 255) / 256, 256>>>(src, dst, ew);
    k_gather<<<(N_NODES + 7) / 8, 256>>>();
    k_gates<<<(N_NODES + 15) / 16, 128>>>(x, h0, c0, Wx, bx, Wh, bh, wc, b, Wl, bl, out);
}

// round 5
// speedup vs baseline: 1.2682x; 1.2682x over previous
#include <cuda_runtime.h>
#include <math.h>

#define N_NODES 50000
#define N_EDGES 1600000
#define HID 32
#define HOR 12

// ---------------- scratch (static device allocation) ----------------
__device__ float g_deg[N_NODES];
__device__ float g_LX[N_NODES * HID];   // L @ X
__device__ float g_Lh[N_NODES * HID];   // L @ h0
__device__ int   g_hflag;               // any(h0 != 0)

// ---------------- deg = segment_sum(w, src); fused h0!=0 probe ----------------
__global__ void k_deg(const int* __restrict__ src,
                      const float* __restrict__ w,
                      const float4* __restrict__ h04) {
    int i = blockIdx.x * blockDim.x + threadIdx.x;
    if (i < N_EDGES) {
        int s = src[i];
        if ((unsigned)s < N_NODES) atomicAdd(&g_deg[s], w[i]);
    }
    if (i < N_NODES * HID / 4) {
        float4 v = h04[i];
        if (v.x != 0.f || v.y != 0.f || v.z != 0.f || v.w != 0.f) g_hflag = 1;
    }
}

// ---------------- edge aggregation: LX[dst] += nw * X[src] ----------------
// one warp = 32 edges, coalesced per-lane edge loads, dinv inline from deg (L1-resident)
__global__ void __launch_bounds__(256) k_edge(
        const int* __restrict__ src,
        const int* __restrict__ dst,
        const float* __restrict__ w,
        const float* __restrict__ x,
        const float* __restrict__ h0) {
    int lane = threadIdx.x & 31;
    long long wid = (long long)(blockIdx.x * blockDim.x + threadIdx.x) >> 5;
    long long e = wid * 32 + lane;

    int s = 0, d = 0;
    float nv = 0.f;
    if (e < N_EDGES) {
        s = src[e];
        d = dst[e];
        if ((unsigned)s < N_NODES && (unsigned)d < N_NODES) {
            float ds = g_deg[s], dd = g_deg[d];
            if (ds > 0.f && dd > 0.f)
                nv = -rsqrtf(ds) * w[e] * rsqrtf(dd);
        }
    }
    int hf = g_hflag;

    #pragma unroll
    for (int i = 0; i < 32; i++) {
        int   si  = __shfl_sync(0xffffffffu, s, i);
        int   di  = __shfl_sync(0xffffffffu, d, i);
        float nvi = __shfl_sync(0xffffffffu, nv, i);
        if (nvi != 0.f) {                         // warp-uniform predicate
            float xv = __ldg(&x[(size_t)si * HID + lane]);
            atomicAdd(&g_LX[di * HID + lane], nvi * xv);
            if (hf) {
                float hv = __ldg(&h0[(size_t)si * HID + lane]);
                atomicAdd(&g_Lh[di * HID + lane], nvi * hv);
            }
        }
    }
}

// ---------------- gates + LSTM cell + head; persistent blocks, Wx loaded once ----------------
#define GBLOCKS 592
__global__ void __launch_bounds__(256) k_gates(
        const float4* __restrict__ x4,
        const float4* __restrict__ h04,
        const float* __restrict__ c0,
        const float* __restrict__ Wx,   // [4][2][32][32]
        const float* __restrict__ bx,
        const float* __restrict__ Wh,
        const float* __restrict__ bh,
        const float* __restrict__ wc,
        const float* __restrict__ b,
        const float* __restrict__ Wl,   // [32][12]
        const float* __restrict__ bl,
        float* __restrict__ out) {
    __shared__ float sWx[8192];          // 32 KB
    __shared__ float sU[32 * 2 * 32];    // 8 KB: !hf [32n][2m][32k] ; hf [16n][4m][32k]
    __shared__ float sWl[HID * HOR];
    __shared__ float sbsum[4 * HID];
    __shared__ float swc[3 * HID];
    __shared__ float sbl[HOR];

    int tid = threadIdx.x;
    int hf = g_hflag;

    for (int i = tid; i < 8192; i += 256) sWx[i] = Wx[i];
    for (int i = tid; i < HID * HOR; i += 256) sWl[i] = Wl[i];
    if (tid < 4 * HID) sbsum[tid] = bx[tid] + bh[tid] + b[tid];
    if (tid < 3 * HID) swc[tid] = wc[tid];
    if (tid < HOR)     sbl[tid] = bl[tid];

    const float4* lx4 = (const float4*)g_LX;
    const float4* lh4 = (const float4*)g_Lh;

    int npt = hf ? 16 : 32;                       // nodes per tile
    int ntiles = (N_NODES + npt - 1) / npt;
    int warp = tid >> 5;
    int j = tid & 31;
    int npw = npt >> 3;                           // nodes per warp (4 or 2)

    float* oh = out;
    float* oH = out + (size_t)N_NODES * HOR;
    float* oC = oH + (size_t)N_NODES * HID;

    for (int tile = blockIdx.x; tile < ntiles; tile += GBLOCKS) {
        int nodeBase = tile * npt;
        __syncthreads();
        // stage U (float4): 512 float4 per tile
        if (!hf) {
            for (int i = tid; i < 512; i += 256) {
                int n = i >> 4, m = (i >> 3) & 1, kq = i & 7;
                int node = nodeBase + n;
                float4 v = make_float4(0.f, 0.f, 0.f, 0.f);
                if (node < N_NODES)
                    v = m ? lx4[node * 8 + kq] : x4[node * 8 + kq];
                ((float4*)sU)[(n * 2 + m) * 8 + kq] = v;
            }
        } else {
            for (int i = tid; i < 512; i += 256) {
                int n = i >> 5, m = (i >> 3) & 3, kq = i & 7;
                int node = nodeBase + n;
                float4 v = make_float4(0.f, 0.f, 0.f, 0.f);
                if (node < N_NODES) {
                    if (m == 0) v = x4[node * 8 + kq];
                    else if (m == 1) v = lx4[node * 8 + kq];
                    else if (m == 2) v = h04[node * 8 + kq];
                    else v = lh4[node * 8 + kq];
                }
                ((float4*)sU)[(n * 4 + m) * 8 + kq] = v;
            }
        }
        __syncthreads();

        float acc[4][4];
        #pragma unroll
        for (int n = 0; n < 4; n++)
            #pragma unroll
            for (int g = 0; g < 4; g++) acc[n][g] = 0.f;

        int nb = warp * npw;
        if (!hf) {
            #pragma unroll
            for (int k = 0; k < 32; k++) {
                float wa[4], wb[4];
                #pragma unroll
                for (int g = 0; g < 4; g++) {
                    wa[g] = sWx[g * 2048 +        k * 32 + j];
                    wb[g] = sWx[g * 2048 + 1024 + k * 32 + j];
                }
                #pragma unroll
                for (int n = 0; n < 4; n++) {
                    float xv  = sU[((nb + n) * 2 + 0) * 32 + k];
                    float lxv = sU[((nb + n) * 2 + 1) * 32 + k];
                    #pragma unroll
                    for (int g = 0; g < 4; g++)
                        acc[n][g] += xv * wa[g] + lxv * wb[g];
                }
            }
        } else {
            #pragma unroll
            for (int k = 0; k < 32; k++) {
                float wa[4], wb[4], wha[4], whb[4];
                #pragma unroll
                for (int g = 0; g < 4; g++) {
                    wa[g]  = sWx[g * 2048 +        k * 32 + j];
                    wb[g]  = sWx[g * 2048 + 1024 + k * 32 + j];
                    wha[g] = __ldg(&Wh[g * 2048 +        k * 32 + j]);
                    whb[g] = __ldg(&Wh[g * 2048 + 1024 + k * 32 + j]);
                }
                #pragma unroll
                for (int n = 0; n < 2; n++) {
                    float xv  = sU[((nb + n) * 4 + 0) * 32 + k];
                    float lxv = sU[((nb + n) * 4 + 1) * 32 + k];
                    float hv  = sU[((nb + n) * 4 + 2) * 32 + k];
                    float lhv = sU[((nb + n) * 4 + 3) * 32 + k];
                    #pragma unroll
                    for (int g = 0; g < 4; g++)
                        acc[n][g] += xv * wa[g] + lxv * wb[g] + hv * wha[g] + lhv * whb[g];
                }
            }
        }

        #pragma unroll
        for (int n = 0; n < 4; n++) {
            if (n >= npw) break;
            int node = nodeBase + nb + n;
            if (node < N_NODES) {
                float c0v = c0[node * HID + j];
                float preI = acc[n][0] + sbsum[0 * 32 + j] + swc[0 * 32 + j] * c0v;
                float preF = acc[n][1] + sbsum[1 * 32 + j] + swc[1 * 32 + j] * c0v;
                float preT = acc[n][2] + sbsum[2 * 32 + j];
                float I  = 1.f / (1.f + __expf(-preI));
                float Fg = 1.f / (1.f + __expf(-preF));
                float T  = tanhf(preT);
                float C  = Fg * c0v + I * T;
                float preO = acc[n][3] + sbsum[3 * 32 + j] + swc[2 * 32 + j] * C;
                float O  = 1.f / (1.f + __expf(-preO));
                float H  = O * tanhf(C);

                oH[node * HID + j] = H;
                oC[node * HID + j] = C;

                // head: h[t] = sum_k relu(H_k)*Wl[k][t] + bl[t]; 32 shfl + 32 FFMA
                float rH = fmaxf(H, 0.f);
                float keep = 0.f;
                #pragma unroll
                for (int k = 0; k < 32; k++) {
                    float rHk = __shfl_sync(0xffffffffu, rH, k);
                    if (j < HOR) keep += rHk * sWl[k * HOR + j];
                }
                if (j < HOR) oh[node * HOR + j] = keep + sbl[j];
            }
        }
    }
}

// ---------------- launch ----------------
extern "C" void kernel_launch(void* const* d_in, const int* in_sizes, int n_in,
                              void* d_out, int out_size) {
    int iX, iEI, iEW, iWx, iBx, iWh, iBh, iWc, iB, iWl, iBl, iH0, iC0;
    if (n_in > 8 && in_sizes[8] == 2 * N_EDGES) {
        iWl = 0; iWh = 1; iWx = 2; iB = 3; iBl = 4; iBh = 5; iBx = 6;
        iC0 = 7; iEI = 8; iEW = 9; iH0 = 10; iWc = 11; iX = 12;
    } else {
        iX = 0; iEI = 1; iEW = 2; iWx = 3; iBx = 4; iWh = 5; iBh = 6;
        iWc = 7; iB = 8; iWl = 9; iBl = 10; iH0 = 11; iC0 = 12;
    }

    const float* x    = (const float*)d_in[iX];
    const int*   ei   = (const int*)d_in[iEI];     // int32 (JAX x64 off)
    const float* ew   = (const float*)d_in[iEW];
    const float* Wx   = (const float*)d_in[iWx];
    const float* bx   = (const float*)d_in[iBx];
    const float* Wh   = (const float*)d_in[iWh];
    const float* bh   = (const float*)d_in[iBh];
    const float* wc   = (const float*)d_in[iWc];
    const float* b    = (const float*)d_in[iB];
    const float* Wl   = (const float*)d_in[iWl];
    const float* bl   = (const float*)d_in[iBl];
    const float* h0   = (const float*)d_in[iH0];
    const float* c0   = (const float*)d_in[iC0];
    float*       out  = (float*)d_out;

    const int* src = ei;
    const int* dst = ei + N_EDGES;

    void *pDeg, *pLX, *pLh, *pFlag;
    cudaGetSymbolAddress(&pDeg,  g_deg);
    cudaGetSymbolAddress(&pLX,   g_LX);
    cudaGetSymbolAddress(&pLh,   g_Lh);
    cudaGetSymbolAddress(&pFlag, g_hflag);
    cudaMemsetAsync(pDeg,  0, N_NODES * sizeof(float));
    cudaMemsetAsync(pLX,   0, N_NODES * HID * sizeof(float));
    cudaMemsetAsync(pLh,   0, N_NODES * HID * sizeof(float));
    cudaMemsetAsync(pFlag, 0, sizeof(int));

    k_deg<<<(N_EDGES + 255) / 256, 256>>>(src, ew, (const float4*)h0);

    long long warps = (N_EDGES + 31) / 32;
    k_edge<<<(int)((warps * 32 + 255) / 256), 256>>>(src, dst, ew, x, h0);

    k_gates<<<GBLOCKS, 256>>>((const float4*)x, (const float4*)h0, c0,
                              Wx, bx, Wh, bh, wc, b, Wl, bl, out);
}

// round 6
// speedup vs baseline: 1.4184x; 1.1184x over previous
#include <cuda_runtime.h>
#include <math.h>

#define N_NODES 50000
#define N_EDGES 1600000
#define HID 32
#define HOR 12

// ---------------- scratch (static device allocation) ----------------
__device__ float g_deg[N_NODES];
__device__ float g_LX[N_NODES * HID];   // L @ X
__device__ float g_Lh[N_NODES * HID];   // L @ h0
__device__ int   g_hflag;               // any(h0 != 0)

// ---------------- deg = segment_sum(w, src); fused h0!=0 probe; 4 edges/thread ----------------
__global__ void __launch_bounds__(256) k_deg(
        const int4* __restrict__ src4,
        const float4* __restrict__ w4,
        const float4* __restrict__ h04) {
    int i = blockIdx.x * blockDim.x + threadIdx.x;     // 400000 threads
    if (i < N_EDGES / 4) {
        int4   s = src4[i];
        float4 w = w4[i];
        if ((unsigned)s.x < N_NODES) atomicAdd(&g_deg[s.x], w.x);
        if ((unsigned)s.y < N_NODES) atomicAdd(&g_deg[s.y], w.y);
        if ((unsigned)s.z < N_NODES) atomicAdd(&g_deg[s.z], w.z);
        if ((unsigned)s.w < N_NODES) atomicAdd(&g_deg[s.w], w.w);
    }
    if (i < N_NODES * HID / 4) {
        float4 v = h04[i];
        if (v.x != 0.f || v.y != 0.f || v.z != 0.f || v.w != 0.f) g_hflag = 1;
    }
}

// ---------------- edge aggregation: LX[dst] += nw * X[src], vectorized RED.128 ----------------
// warp = 32 edges. lanes regrouped: sub=lane>>3 picks edge within group-of-4, q=lane&7 feature quad.
__global__ void __launch_bounds__(256) k_edge(
        const int* __restrict__ src,
        const int* __restrict__ dst,
        const float* __restrict__ w,
        const float4* __restrict__ x4,
        const float4* __restrict__ h04) {
    int lane = threadIdx.x & 31;
    long long wid = (long long)(blockIdx.x * blockDim.x + threadIdx.x) >> 5;
    long long e = wid * 32 + lane;

    int s = 0, d = 0;
    float nv = 0.f;
    if (e < N_EDGES) {
        s = src[e];
        d = dst[e];
        if ((unsigned)s < N_NODES && (unsigned)d < N_NODES) {
            float ds = g_deg[s], dd = g_deg[d];
            if (ds > 0.f && dd > 0.f)
                nv = -rsqrtf(ds) * w[e] * rsqrtf(dd);
        }
    }
    int hf = g_hflag;
    int sub = lane >> 3;     // edge-in-group 0..3
    int q   = lane & 7;      // feature quad 0..7

    #pragma unroll
    for (int it = 0; it < 8; it++) {
        int srcLane = it * 4 + sub;
        int   si  = __shfl_sync(0xffffffffu, s, srcLane);
        int   di  = __shfl_sync(0xffffffffu, d, srcLane);
        float nvi = __shfl_sync(0xffffffffu, nv, srcLane);
        if (nvi != 0.f) {
            float4 xv = __ldg(&x4[(size_t)si * 8 + q]);
            asm volatile("red.global.add.v4.f32 [%0], {%1,%2,%3,%4};"
                         :: "l"(&g_LX[di * HID + q * 4]),
                            "f"(nvi * xv.x), "f"(nvi * xv.y),
                            "f"(nvi * xv.z), "f"(nvi * xv.w)
                         : "memory");
            if (hf) {
                float4 hv = __ldg(&h04[(size_t)si * 8 + q]);
                asm volatile("red.global.add.v4.f32 [%0], {%1,%2,%3,%4};"
                             :: "l"(&g_Lh[di * HID + q * 4]),
                                "f"(nvi * hv.x), "f"(nvi * hv.y),
                                "f"(nvi * hv.z), "f"(nvi * hv.w)
                             : "memory");
            }
        }
    }
}

// ---------------- gates + LSTM cell + head; persistent blocks, Wx loaded once ----------------
#define GBLOCKS 592
__global__ void __launch_bounds__(256) k_gates(
        const float4* __restrict__ x4,
        const float4* __restrict__ h04,
        const float* __restrict__ c0,
        const float* __restrict__ Wx,   // [4][2][32][32]
        const float* __restrict__ bx,
        const float* __restrict__ Wh,
        const float* __restrict__ bh,
        const float* __restrict__ wc,
        const float* __restrict__ b,
        const float* __restrict__ Wl,   // [32][12]
        const float* __restrict__ bl,
        float* __restrict__ out) {
    __shared__ float sWx[8192];          // 32 KB
    __shared__ float sU[32 * 2 * 32];    // 8 KB
    __shared__ float sWl[HID * HOR];
    __shared__ float sbsum[4 * HID];
    __shared__ float swc[3 * HID];
    __shared__ float sbl[HOR];

    int tid = threadIdx.x;
    int hf = g_hflag;

    for (int i = tid; i < 8192; i += 256) sWx[i] = Wx[i];
    for (int i = tid; i < HID * HOR; i += 256) sWl[i] = Wl[i];
    if (tid < 4 * HID) sbsum[tid] = bx[tid] + bh[tid] + b[tid];
    if (tid < 3 * HID) swc[tid] = wc[tid];
    if (tid < HOR)     sbl[tid] = bl[tid];

    const float4* lx4 = (const float4*)g_LX;
    const float4* lh4 = (const float4*)g_Lh;

    int npt = hf ? 16 : 32;
    int ntiles = (N_NODES + npt - 1) / npt;
    int warp = tid >> 5;
    int j = tid & 31;
    int npw = npt >> 3;

    float* oh = out;
    float* oH = out + (size_t)N_NODES * HOR;
    float* oC = oH + (size_t)N_NODES * HID;

    for (int tile = blockIdx.x; tile < ntiles; tile += GBLOCKS) {
        int nodeBase = tile * npt;
        __syncthreads();
        if (!hf) {
            for (int i = tid; i < 512; i += 256) {
                int n = i >> 4, m = (i >> 3) & 1, kq = i & 7;
                int node = nodeBase + n;
                float4 v = make_float4(0.f, 0.f, 0.f, 0.f);
                if (node < N_NODES)
                    v = m ? lx4[node * 8 + kq] : x4[node * 8 + kq];
                ((float4*)sU)[(n * 2 + m) * 8 + kq] = v;
            }
        } else {
            for (int i = tid; i < 512; i += 256) {
                int n = i >> 5, m = (i >> 3) & 3, kq = i & 7;
                int node = nodeBase + n;
                float4 v = make_float4(0.f, 0.f, 0.f, 0.f);
                if (node < N_NODES) {
                    if (m == 0) v = x4[node * 8 + kq];
                    else if (m == 1) v = lx4[node * 8 + kq];
                    else if (m == 2) v = h04[node * 8 + kq];
                    else v = lh4[node * 8 + kq];
                }
                ((float4*)sU)[(n * 4 + m) * 8 + kq] = v;
            }
        }
        __syncthreads();

        float acc[4][4];
        #pragma unroll
        for (int n = 0; n < 4; n++)
            #pragma unroll
            for (int g = 0; g < 4; g++) acc[n][g] = 0.f;

        int nb = warp * npw;
        if (!hf) {
            #pragma unroll
            for (int k = 0; k < 32; k++) {
                float wa[4], wb[4];
                #pragma unroll
                for (int g = 0; g < 4; g++) {
                    wa[g] = sWx[g * 2048 +        k * 32 + j];
                    wb[g] = sWx[g * 2048 + 1024 + k * 32 + j];
                }
                #pragma unroll
                for (int n = 0; n < 4; n++) {
                    float xv  = sU[((nb + n) * 2 + 0) * 32 + k];
                    float lxv = sU[((nb + n) * 2 + 1) * 32 + k];
                    #pragma unroll
                    for (int g = 0; g < 4; g++)
                        acc[n][g] += xv * wa[g] + lxv * wb[g];
                }
            }
        } else {
            #pragma unroll
            for (int k = 0; k < 32; k++) {
                float wa[4], wb[4], wha[4], whb[4];
                #pragma unroll
                for (int g = 0; g < 4; g++) {
                    wa[g]  = sWx[g * 2048 +        k * 32 + j];
                    wb[g]  = sWx[g * 2048 + 1024 + k * 32 + j];
                    wha[g] = __ldg(&Wh[g * 2048 +        k * 32 + j]);
                    whb[g] = __ldg(&Wh[g * 2048 + 1024 + k * 32 + j]);
                }
                #pragma unroll
                for (int n = 0; n < 2; n++) {
                    float xv  = sU[((nb + n) * 4 + 0) * 32 + k];
                    float lxv = sU[((nb + n) * 4 + 1) * 32 + k];
                    float hv  = sU[((nb + n) * 4 + 2) * 32 + k];
                    float lhv = sU[((nb + n) * 4 + 3) * 32 + k];
                    #pragma unroll
                    for (int g = 0; g < 4; g++)
                        acc[n][g] += xv * wa[g] + lxv * wb[g] + hv * wha[g] + lhv * whb[g];
                }
            }
        }

        #pragma unroll
        for (int n = 0; n < 4; n++) {
            if (n >= npw) break;
            int node = nodeBase + nb + n;
            if (node < N_NODES) {
                float c0v = c0[node * HID + j];
                float preI = acc[n][0] + sbsum[0 * 32 + j] + swc[0 * 32 + j] * c0v;
                float preF = acc[n][1] + sbsum[1 * 32 + j] + swc[1 * 32 + j] * c0v;
                float preT = acc[n][2] + sbsum[2 * 32 + j];
                float I  = 1.f / (1.f + __expf(-preI));
                float Fg = 1.f / (1.f + __expf(-preF));
                float T  = tanhf(preT);
                float C  = Fg * c0v + I * T;
                float preO = acc[n][3] + sbsum[3 * 32 + j] + swc[2 * 32 + j] * C;
                float O  = 1.f / (1.f + __expf(-preO));
                float H  = O * tanhf(C);

                oH[node * HID + j] = H;
                oC[node * HID + j] = C;

                float rH = fmaxf(H, 0.f);
                float keep = 0.f;
                #pragma unroll
                for (int k = 0; k < 32; k++) {
                    float rHk = __shfl_sync(0xffffffffu, rH, k);
                    if (j < HOR) keep += rHk * sWl[k * HOR + j];
                }
                if (j < HOR) oh[node * HOR + j] = keep + sbl[j];
            }
        }
    }
}

// ---------------- launch ----------------
extern "C" void kernel_launch(void* const* d_in, const int* in_sizes, int n_in,
                              void* d_out, int out_size) {
    int iX, iEI, iEW, iWx, iBx, iWh, iBh, iWc, iB, iWl, iBl, iH0, iC0;
    if (n_in > 8 && in_sizes[8] == 2 * N_EDGES) {
        iWl = 0; iWh = 1; iWx = 2; iB = 3; iBl = 4; iBh = 5; iBx = 6;
        iC0 = 7; iEI = 8; iEW = 9; iH0 = 10; iWc = 11; iX = 12;
    } else {
        iX = 0; iEI = 1; iEW = 2; iWx = 3; iBx = 4; iWh = 5; iBh = 6;
        iWc = 7; iB = 8; iWl = 9; iBl = 10; iH0 = 11; iC0 = 12;
    }

    const float* x    = (const float*)d_in[iX];
    const int*   ei   = (const int*)d_in[iEI];     // int32 (JAX x64 off)
    const float* ew   = (const float*)d_in[iEW];
    const float* Wx   = (const float*)d_in[iWx];
    const float* bx   = (const float*)d_in[iBx];
    const float* Wh   = (const float*)d_in[iWh];
    const float* bh   = (const float*)d_in[iBh];
    const float* wc   = (const float*)d_in[iWc];
    const float* b    = (const float*)d_in[iB];
    const float* Wl   = (const float*)d_in[iWl];
    const float* bl   = (const float*)d_in[iBl];
    const float* h0   = (const float*)d_in[iH0];
    const float* c0   = (const float*)d_in[iC0];
    float*       out  = (float*)d_out;

    const int* src = ei;
    const int* dst = ei + N_EDGES;

    void *pDeg, *pLX, *pLh, *pFlag;
    cudaGetSymbolAddress(&pDeg,  g_deg);
    cudaGetSymbolAddress(&pLX,   g_LX);
    cudaGetSymbolAddress(&pLh,   g_Lh);
    cudaGetSymbolAddress(&pFlag, g_hflag);
    cudaMemsetAsync(pDeg,  0, N_NODES * sizeof(float));
    cudaMemsetAsync(pLX,   0, N_NODES * HID * sizeof(float));
    cudaMemsetAsync(pLh,   0, N_NODES * HID * sizeof(float));
    cudaMemsetAsync(pFlag, 0, sizeof(int));

    k_deg<<<(N_NODES * HID / 4 + 255) / 256, 256>>>(
        (const int4*)src, (const float4*)ew, (const float4*)h0);

    long long warps = (N_EDGES + 31) / 32;
    k_edge<<<(int)((warps * 32 + 255) / 256), 256>>>(
        src, dst, ew, (const float4*)x, (const float4*)h0);

    k_gates<<<GBLOCKS, 256>>>((const float4*)x, (const float4*)h0, c0,
                              Wx, bx, Wh, bh, wc, b, Wl, bl, out);
}